// round 4
// baseline (speedup 1.0000x reference)
#include <cuda_runtime.h>

#define E_EDGES 100000
#define M_PAIRS 1000000

// ---------------- device scratch (static, no allocation) ----------------
__device__ float g_WkA[128 * 8];      // folded Wk @ Aw  [in][h]
__device__ float g_bkA[8];            // folded bk . Aw  [h]
__device__ float g_kA[E_EDGES * 8];   // per-edge key score [e][h]
__device__ float g_Vh[(size_t)E_EDGES * 128];  // V projection [e][h*16+d]
__device__ int   g_counts[E_EDGES];
__device__ int   g_offsets[E_EDGES + 1];
__device__ int   g_cursor[E_EDGES];
__device__ int   g_perm[M_PAIRS];     // src ids grouped by dst
__device__ int   g_src[M_PAIRS];      // decoded src indices
__device__ int   g_dst[M_PAIRS];      // decoded dst indices
__device__ int   g_bsum[512];
__device__ int   g_boff[512];
__device__ int   g_is64;              // 1 if index buffer is int64

// ---------------- K-1a: detect index dtype ----------------
// If int64: first 2M words = src row as (low,0) pairs -> all odd words zero.
// If int32: first 2M words = src row + dst row, odd words random in [0,1e5).
__global__ void detect_kernel(const int* __restrict__ w) {
    int i = blockIdx.x * blockDim.x + threadIdx.x;   // odd-word index
    if (i < M_PAIRS) {
        if (w[2 * i + 1] != 0) g_is64 = 0;   // any nonzero odd word => int32
    }
}

// ---------------- K-1b: decode indices (branch on detected dtype) -------
__global__ void decode_kernel(const int* __restrict__ w) {
    int i = blockIdx.x * blockDim.x + threadIdx.x;
    if (i >= M_PAIRS) return;
    int s, d;
    if (g_is64) {
        s = w[2 * i];                       // low word of int64 src[i]
        d = w[2 * M_PAIRS + 2 * i];         // low word of int64 dst[i]
    } else {
        s = w[i];
        d = w[M_PAIRS + i];
    }
    // clamp: wrong results are debuggable, address-space traps are not
    s = min(max(s, 0), E_EDGES - 1);
    d = min(max(d, 0), E_EDGES - 1);
    g_src[i] = s;
    g_dst[i] = d;
}

// ---------------- K0: fold Wk*Aw, zero counts, init flag ----------------
__global__ void prep_kernel(const float* __restrict__ Wk,
                            const float* __restrict__ bk,
                            const float* __restrict__ Aw) {
    int idx = blockIdx.x * blockDim.x + threadIdx.x;
    if (idx < E_EDGES) g_counts[idx] = 0;
    if (idx == 0) g_is64 = 1;
    if (blockIdx.x == 0) {
        int t = threadIdx.x;
        if (t < 128) {
            #pragma unroll
            for (int h = 0; h < 8; h++) {
                float s = 0.f;
                #pragma unroll
                for (int d = 0; d < 16; d++)
                    s += Wk[t * 128 + h * 16 + d] * Aw[d * 8 + h];
                g_WkA[t * 8 + h] = s;
            }
        }
        if (t < 8) {
            float s = 0.f;
            #pragma unroll
            for (int d = 0; d < 16; d++)
                s += bk[t * 16 + d] * Aw[d * 8 + t];
            g_bkA[t] = s;
        }
    }
}

// ---------------- K1: V projection GEMM (plain fp32 FMA, static smem) ----
__global__ void gemm_v_kernel(const float* __restrict__ attr,
                              const float* __restrict__ Wv,
                              const float* __restrict__ bv) {
    __shared__ float Ws[32][128];   // 16 KB
    __shared__ float As[64][36];    // padded rows
    int t = threadIdx.x;
    int row0 = blockIdx.x * 64;
    int c4 = (t & 31) * 4;          // output column base
    int rg = t >> 5;                // row group 0..7

    float4 acc[8];
    #pragma unroll
    for (int r = 0; r < 8; r++) acc[r] = make_float4(0.f, 0.f, 0.f, 0.f);

    for (int k0 = 0; k0 < 128; k0 += 32) {
        __syncthreads();
        #pragma unroll
        for (int i = t; i < 512; i += 256) {
            int r = i >> 3, q = i & 7;
            float4 v = make_float4(0.f, 0.f, 0.f, 0.f);
            if (row0 + r < E_EDGES)
                v = ((const float4*)attr)[(size_t)(row0 + r) * 32 + (k0 >> 2) + q];
            *(float4*)&As[r][q * 4] = v;
        }
        #pragma unroll
        for (int i = t; i < 1024; i += 256) {
            int k = i >> 5, q = i & 31;
            *(float4*)&Ws[k][q * 4] = ((const float4*)Wv)[(size_t)(k0 + k) * 32 + q];
        }
        __syncthreads();

        #pragma unroll
        for (int k = 0; k < 32; k++) {
            float4 w = *(const float4*)&Ws[k][c4];
            #pragma unroll
            for (int r = 0; r < 8; r++) {
                float a = As[rg * 8 + r][k];
                acc[r].x = fmaf(a, w.x, acc[r].x);
                acc[r].y = fmaf(a, w.y, acc[r].y);
                acc[r].z = fmaf(a, w.z, acc[r].z);
                acc[r].w = fmaf(a, w.w, acc[r].w);
            }
        }
    }

    float4 bvv = ((const float4*)bv)[t & 31];
    #pragma unroll
    for (int r = 0; r < 8; r++) {
        int row = row0 + rg * 8 + r;
        if (row < E_EDGES) {
            float4 o = make_float4(acc[r].x + bvv.x, acc[r].y + bvv.y,
                                   acc[r].z + bvv.z, acc[r].w + bvv.w);
            *(float4*)&g_Vh[(size_t)row * 128 + c4] = o;
        }
    }
}

// ---------------- K2: kA = attr @ WkA + bkA ----------------
__global__ void ka_kernel(const float* __restrict__ attr) {
    __shared__ float sA[32][132];
    __shared__ float sW[1024];
    int t = threadIdx.x;
    for (int i = t; i < 1024; i += 256) sW[i] = g_WkA[i];
    int row0 = blockIdx.x * 32;
    for (int i = t; i < 1024; i += 256) {
        int r = i >> 5, kq = i & 31;
        float4 v = make_float4(0.f, 0.f, 0.f, 0.f);
        if (row0 + r < E_EDGES)
            v = ((const float4*)attr)[(size_t)(row0 + r) * 32 + kq];
        sA[r][kq * 4 + 0] = v.x; sA[r][kq * 4 + 1] = v.y;
        sA[r][kq * 4 + 2] = v.z; sA[r][kq * 4 + 3] = v.w;
    }
    __syncthreads();
    int r = t >> 3, h = t & 7;
    int e = row0 + r;
    if (e < E_EDGES) {
        float acc = g_bkA[h];
        #pragma unroll 16
        for (int k = 0; k < 128; k++)
            acc += sA[r][k] * sW[k * 8 + h];
        g_kA[e * 8 + h] = acc;
    }
}

// ---------------- K3: histogram over dst ----------------
__global__ void hist_kernel() {
    int i = blockIdx.x * blockDim.x + threadIdx.x;
    if (i < M_PAIRS) atomicAdd(&g_counts[g_dst[i]], 1);
}

// ---------------- K4: 3-kernel exclusive scan ----------------
__global__ void scan_a() {
    int i = blockIdx.x * 256 + threadIdx.x;
    int v = (i < E_EDGES) ? g_counts[i] : 0;
    __shared__ int smw[8];
    for (int o = 16; o; o >>= 1) v += __shfl_down_sync(~0u, v, o);
    if ((threadIdx.x & 31) == 0) smw[threadIdx.x >> 5] = v;
    __syncthreads();
    if (threadIdx.x == 0) {
        int s = 0;
        #pragma unroll
        for (int w = 0; w < 8; w++) s += smw[w];
        g_bsum[blockIdx.x] = s;
    }
}

__global__ void scan_b() {  // single block over 391 block sums
    int t = threadIdx.x;
    int v = (t < 391) ? g_bsum[t] : 0;
    int lane = t & 31, w = t >> 5;
    int inc = v;
    for (int o = 1; o < 32; o <<= 1) {
        int x = __shfl_up_sync(~0u, inc, o);
        if (lane >= o) inc += x;
    }
    __shared__ int ws[16];
    if (lane == 31) ws[w] = inc;
    __syncthreads();
    if (w == 0) {
        int s = (lane < 16) ? ws[lane] : 0;
        int inc2 = s;
        for (int o = 1; o < 16; o <<= 1) {
            int x = __shfl_up_sync(~0u, inc2, o);
            if (lane >= o) inc2 += x;
        }
        if (lane < 16) ws[lane] = inc2 - s;
    }
    __syncthreads();
    if (t < 391) g_boff[t] = ws[w] + inc - v;
    if (t == 0) g_offsets[E_EDGES] = M_PAIRS;
}

__global__ void scan_c() {
    int i = blockIdx.x * 256 + threadIdx.x;
    int v = (i < E_EDGES) ? g_counts[i] : 0;
    int lane = threadIdx.x & 31, w = threadIdx.x >> 5;
    int inc = v;
    for (int o = 1; o < 32; o <<= 1) {
        int x = __shfl_up_sync(~0u, inc, o);
        if (lane >= o) inc += x;
    }
    __shared__ int ws[8];
    if (lane == 31) ws[w] = inc;
    __syncthreads();
    if (w == 0 && lane < 8) {
        int s = ws[lane];
        int inc2 = s;
        for (int o = 1; o < 8; o <<= 1) {
            int x = __shfl_up_sync(0xffu, inc2, o);
            if (lane >= o) inc2 += x;
        }
        ws[lane] = inc2 - s;
    }
    __syncthreads();
    int excl = g_boff[blockIdx.x] + ws[w] + inc - v;
    if (i < E_EDGES) { g_offsets[i] = excl; g_cursor[i] = excl; }
}

// ---------------- K5: scatter src into CSR ----------------
__global__ void scatter_kernel() {
    int i = blockIdx.x * blockDim.x + threadIdx.x;
    if (i < M_PAIRS) {
        int pos = atomicAdd(&g_cursor[g_dst[i]], 1);
        g_perm[pos] = g_src[i];
    }
}

// ---------------- K6: per-dst warp — online softmax + weighted V sum ----
__global__ void agg_kernel(float* __restrict__ out) {
    int gw = (blockIdx.x * blockDim.x + threadIdx.x) >> 5;
    int lane = threadIdx.x & 31;
    if (gw >= E_EDGES) return;
    int beg = g_offsets[gw], end = g_offsets[gw + 1];
    const float NEG_INF = __int_as_float(0xff800000);
    int h_s = lane & 7;     // stats view: lane = pair*8 + h
    int h_a = lane >> 2;    // accum view: lane = h*4 + dquad
    float4 acc = make_float4(0.f, 0.f, 0.f, 0.f);
    float mrun = NEG_INF, srun = 0.f;

    for (int base = beg; base < end; base += 4) {
        int n = end - base; if (n > 4) n = 4;
        int p = lane >> 3;
        int s = 0;
        float x = NEG_INF;
        if (p < n) {
            s = g_perm[base + p];
            x = g_kA[s * 8 + h_s];
        }
        float cm = fmaxf(x, __shfl_xor_sync(~0u, x, 8));
        cm = fmaxf(cm, __shfl_xor_sync(~0u, cm, 16));
        float mnew = fmaxf(mrun, cm);
        float fsc = __expf(mrun - mnew);   // 0 when mrun==-inf
        float ex = __expf(x - mnew);       // 0 for invalid lanes
        float cs = ex + __shfl_xor_sync(~0u, ex, 8);
        cs += __shfl_xor_sync(~0u, cs, 16);
        srun = srun * fsc + cs;
        mrun = mnew;
        float f2 = __shfl_sync(~0u, fsc, h_a);
        acc.x *= f2; acc.y *= f2; acc.z *= f2; acc.w *= f2;
        #pragma unroll
        for (int q = 0; q < 4; q++) {
            if (q >= n) break;                       // uniform across warp
            float wq = __shfl_sync(~0u, ex, q * 8 + h_a);
            int sq = __shfl_sync(~0u, s, q * 8);
            float4 v = *(const float4*)&g_Vh[(size_t)sq * 128 + lane * 4];
            acc.x += wq * v.x; acc.y += wq * v.y;
            acc.z += wq * v.z; acc.w += wq * v.w;
        }
    }
    float denom = __shfl_sync(~0u, srun, h_a) + 1e-16f;
    float inv = 1.f / denom;
    float4 o = make_float4(acc.x * inv, acc.y * inv, acc.z * inv, acc.w * inv);
    ((float4*)out)[(size_t)gw * 32 + lane] = o;
}

// ---------------- launch ----------------
extern "C" void kernel_launch(void* const* d_in, const int* in_sizes, int n_in,
                              void* d_out, int out_size) {
    const float* attr = (const float*)d_in[0];
    const int*   eeiw = (const int*)d_in[1];   // index buffer viewed as words
    // d_in[2]=Wq, d_in[3]=bq : algebraically cancelled in segment softmax.
    const float* Wk   = (const float*)d_in[4];
    const float* bk   = (const float*)d_in[5];
    const float* Wv   = (const float*)d_in[6];
    const float* bv   = (const float*)d_in[7];
    const float* Aw   = (const float*)d_in[8];
    float*       out  = (float*)d_out;

    prep_kernel   <<<391, 256>>>(Wk, bk, Aw);
    detect_kernel <<<3907, 256>>>(eeiw);
    decode_kernel <<<3907, 256>>>(eeiw);
    gemm_v_kernel <<<1563, 256>>>(attr, Wv, bv);
    ka_kernel     <<<3125, 256>>>(attr);
    hist_kernel   <<<3907, 256>>>();
    scan_a        <<<391, 256>>>();
    scan_b        <<<1, 512>>>();
    scan_c        <<<391, 256>>>();
    scatter_kernel<<<3907, 256>>>();
    agg_kernel    <<<12500, 256>>>(out);

    (void)in_sizes; (void)n_in; (void)out_size;
}

// round 9
// speedup vs baseline: 1.0146x; 1.0146x over previous
#include <cuda_runtime.h>

#define E_EDGES 100000
#define M_PAIRS 1000000

// ---------------- device scratch (static, no allocation) ----------------
__device__ float g_WkA[128 * 8];      // folded Wk @ Aw  [in][h]
__device__ float g_bkA[8];            // folded bk . Aw  [h]
__device__ float g_kA[E_EDGES * 8];   // per-edge key score [e][h]
__device__ float g_Vh[(size_t)E_EDGES * 128];  // V projection [e][h*16+d]
__device__ int   g_counts[E_EDGES];
__device__ int   g_offsets[E_EDGES + 1];
__device__ int   g_cursor[E_EDGES];
__device__ int   g_perm[M_PAIRS];     // src ids grouped by dst
__device__ int   g_src[M_PAIRS];      // decoded src indices
__device__ int   g_dst[M_PAIRS];      // decoded dst indices
__device__ int   g_bsum[512];
__device__ int   g_boff[512];
__device__ int   g_is64;              // 1 if index buffer is int64

// ---------------- f32x2 FMA helper (PTX-only path) ----------------------
__device__ __forceinline__ void fma2(unsigned long long& d,
                                     unsigned long long a,
                                     unsigned long long b) {
    asm("fma.rn.f32x2 %0, %1, %2, %0;" : "+l"(d) : "l"(a), "l"(b));
}

// ---------------- K-1a: detect index dtype ----------------
__global__ void detect_kernel(const int* __restrict__ w) {
    int i = blockIdx.x * blockDim.x + threadIdx.x;
    if (i < M_PAIRS) {
        if (w[2 * i + 1] != 0) g_is64 = 0;   // any nonzero odd word => int32
    }
}

// ---------------- K-1b: decode indices + fused histogram ----------------
__global__ void decode_kernel(const int* __restrict__ w) {
    int i = blockIdx.x * blockDim.x + threadIdx.x;
    if (i >= M_PAIRS) return;
    int s, d;
    if (g_is64) {
        s = w[2 * i];
        d = w[2 * M_PAIRS + 2 * i];
    } else {
        s = w[i];
        d = w[M_PAIRS + i];
    }
    s = min(max(s, 0), E_EDGES - 1);
    d = min(max(d, 0), E_EDGES - 1);
    g_src[i] = s;
    g_dst[i] = d;
    atomicAdd(&g_counts[d], 1);           // fused histogram
}

// ---------------- K0: fold Wk*Aw, zero counts, init flag ----------------
__global__ void prep_kernel(const float* __restrict__ Wk,
                            const float* __restrict__ bk,
                            const float* __restrict__ Aw) {
    int idx = blockIdx.x * blockDim.x + threadIdx.x;
    if (idx < E_EDGES) g_counts[idx] = 0;
    if (idx == 0) g_is64 = 1;
    if (blockIdx.x == 0) {
        int t = threadIdx.x;
        if (t < 128) {
            #pragma unroll
            for (int h = 0; h < 8; h++) {
                float s = 0.f;
                #pragma unroll
                for (int d = 0; d < 16; d++)
                    s += Wk[t * 128 + h * 16 + d] * Aw[d * 8 + h];
                g_WkA[t * 8 + h] = s;
            }
        }
        if (t < 8) {
            float s = 0.f;
            #pragma unroll
            for (int d = 0; d < 16; d++)
                s += bk[t * 16 + d] * Aw[d * 8 + t];
            g_bkA[t] = s;
        }
    }
}

// ---------------- K1: fused V GEMM (f32x2) + kA projection ----------------
// block: 256 threads = 8 warps. 64 rows x 128 cols, k chunked by 32.
// A tile stored duplicated (a,a); row stride 68 floats = 272B (16-multiple)
// so STS.128 fills and LDS.64 broadcast reads are both aligned.
__global__ void gemm_v_kernel(const float* __restrict__ attr,
                              const float* __restrict__ Wv,
                              const float* __restrict__ bv) {
    __shared__ __align__(16) float Ws[32][128];    // 16 KB
    __shared__ __align__(16) float As2[64][68];    // 17.4 KB
    __shared__ __align__(16) float sKA[32][8];     // 1 KB

    int t = threadIdx.x;
    int row0 = blockIdx.x * 64;
    int c4 = (t & 31) * 4;           // output column base
    int rg = t >> 5;                 // warp id = row group (warp-uniform)

    unsigned long long acc01[8], acc23[8];
    #pragma unroll
    for (int r = 0; r < 8; r++) { acc01[r] = 0ull; acc23[r] = 0ull; }

    // fused kA accumulators: thread -> (row = t>>2, heads h0, h0+1)
    int krow = t >> 2;
    int h0 = (t & 3) * 2;
    float kacc0 = 0.f, kacc1 = 0.f;

    for (int k0 = 0; k0 < 128; k0 += 32) {
        __syncthreads();
        // A chunk: 64 rows x 32 k, duplicated pairs
        #pragma unroll
        for (int i = t; i < 512; i += 256) {
            int r = i >> 3, q = i & 7;
            float4 v = make_float4(0.f, 0.f, 0.f, 0.f);
            if (row0 + r < E_EDGES)
                v = ((const float4*)attr)[(size_t)(row0 + r) * 32 + (k0 >> 2) + q];
            float4 d0 = make_float4(v.x, v.x, v.y, v.y);
            float4 d1 = make_float4(v.z, v.z, v.w, v.w);
            *(float4*)&As2[r][q * 8]     = d0;
            *(float4*)&As2[r][q * 8 + 4] = d1;
        }
        // W chunk: 32 k x 128 cols
        #pragma unroll
        for (int i = t; i < 1024; i += 256) {
            int k = i >> 5, q = i & 31;
            *(float4*)&Ws[k][q * 4] = ((const float4*)Wv)[(size_t)(k0 + k) * 32 + q];
        }
        // WkA chunk: 32 k x 8 heads
        if (t < 256) sKA[t >> 3][t & 7] = g_WkA[(k0 + (t >> 3)) * 8 + (t & 7)];
        __syncthreads();

        #pragma unroll 8
        for (int k = 0; k < 32; k++) {
            float4 w = *(const float4*)&Ws[k][c4];
            unsigned long long w01, w23;
            asm("mov.b64 %0, {%1, %2};" : "=l"(w01) : "f"(w.x), "f"(w.y));
            asm("mov.b64 %0, {%1, %2};" : "=l"(w23) : "f"(w.z), "f"(w.w));
            const float* arowbase = &As2[rg * 8][2 * k];
            #pragma unroll
            for (int r = 0; r < 8; r++) {
                unsigned long long pa =
                    *(const unsigned long long*)(arowbase + r * 68);
                fma2(acc01[r], pa, w01);
                fma2(acc23[r], pa, w23);
            }
        }

        // fused kA partial for this chunk
        #pragma unroll 8
        for (int k = 0; k < 32; k++) {
            float a = As2[krow][2 * k];
            kacc0 = fmaf(a, sKA[k][h0], kacc0);
            kacc1 = fmaf(a, sKA[k][h0 + 1], kacc1);
        }
    }

    float4 bvv = ((const float4*)bv)[t & 31];
    #pragma unroll
    for (int r = 0; r < 8; r++) {
        int row = row0 + rg * 8 + r;
        if (row < E_EDGES) {
            float2 u0 = *(float2*)&acc01[r];
            float2 u1 = *(float2*)&acc23[r];
            float4 o = make_float4(u0.x + bvv.x, u0.y + bvv.y,
                                   u1.x + bvv.z, u1.y + bvv.w);
            *(float4*)&g_Vh[(size_t)row * 128 + c4] = o;
        }
    }
    int ke = row0 + krow;
    if (ke < E_EDGES) {
        g_kA[ke * 8 + h0]     = kacc0 + g_bkA[h0];
        g_kA[ke * 8 + h0 + 1] = kacc1 + g_bkA[h0 + 1];
    }
}

// ---------------- K4: 3-kernel exclusive scan ----------------
__global__ void scan_a() {
    int i = blockIdx.x * 256 + threadIdx.x;
    int v = (i < E_EDGES) ? g_counts[i] : 0;
    __shared__ int smw[8];
    for (int o = 16; o; o >>= 1) v += __shfl_down_sync(~0u, v, o);
    if ((threadIdx.x & 31) == 0) smw[threadIdx.x >> 5] = v;
    __syncthreads();
    if (threadIdx.x == 0) {
        int s = 0;
        #pragma unroll
        for (int w = 0; w < 8; w++) s += smw[w];
        g_bsum[blockIdx.x] = s;
    }
}

__global__ void scan_b() {  // single block over 391 block sums
    int t = threadIdx.x;
    int v = (t < 391) ? g_bsum[t] : 0;
    int lane = t & 31, w = t >> 5;
    int inc = v;
    for (int o = 1; o < 32; o <<= 1) {
        int x = __shfl_up_sync(~0u, inc, o);
        if (lane >= o) inc += x;
    }
    __shared__ int ws[16];
    if (lane == 31) ws[w] = inc;
    __syncthreads();
    if (w == 0) {
        int s = (lane < 16) ? ws[lane] : 0;
        int inc2 = s;
        for (int o = 1; o < 16; o <<= 1) {
            int x = __shfl_up_sync(~0u, inc2, o);
            if (lane >= o) inc2 += x;
        }
        if (lane < 16) ws[lane] = inc2 - s;
    }
    __syncthreads();
    if (t < 391) g_boff[t] = ws[w] + inc - v;
    if (t == 0) g_offsets[E_EDGES] = M_PAIRS;
}

__global__ void scan_c() {
    int i = blockIdx.x * 256 + threadIdx.x;
    int v = (i < E_EDGES) ? g_counts[i] : 0;
    int lane = threadIdx.x & 31, w = threadIdx.x >> 5;
    int inc = v;
    for (int o = 1; o < 32; o <<= 1) {
        int x = __shfl_up_sync(~0u, inc, o);
        if (lane >= o) inc += x;
    }
    __shared__ int ws[8];
    if (lane == 31) ws[w] = inc;
    __syncthreads();
    if (w == 0 && lane < 8) {
        int s = ws[lane];
        int inc2 = s;
        for (int o = 1; o < 8; o <<= 1) {
            int x = __shfl_up_sync(0xffu, inc2, o);
            if (lane >= o) inc2 += x;
        }
        ws[lane] = inc2 - s;
    }
    __syncthreads();
    int excl = g_boff[blockIdx.x] + ws[w] + inc - v;
    if (i < E_EDGES) { g_offsets[i] = excl; g_cursor[i] = excl; }
}

// ---------------- K5: scatter src into CSR ----------------
__global__ void scatter_kernel() {
    int i = blockIdx.x * blockDim.x + threadIdx.x;
    if (i < M_PAIRS) {
        int pos = atomicAdd(&g_cursor[g_dst[i]], 1);
        g_perm[pos] = g_src[i];
    }
}

// ---------------- K6: per-dst warp — online softmax + weighted V sum ----
__global__ void agg_kernel(float* __restrict__ out) {
    int gw = (blockIdx.x * blockDim.x + threadIdx.x) >> 5;
    int lane = threadIdx.x & 31;
    if (gw >= E_EDGES) return;
    int beg = g_offsets[gw], end = g_offsets[gw + 1];
    const float NEG_INF = __int_as_float(0xff800000);
    int h_s = lane & 7;     // stats view: lane = pair*8 + h
    int h_a = lane >> 2;    // accum view: lane = h*4 + dquad
    float4 acc = make_float4(0.f, 0.f, 0.f, 0.f);
    float mrun = NEG_INF, srun = 0.f;

    for (int base = beg; base < end; base += 4) {
        int n = end - base; if (n > 4) n = 4;
        int p = lane >> 3;
        int s = 0;
        float x = NEG_INF;
        if (p < n) {
            s = g_perm[base + p];
            x = g_kA[s * 8 + h_s];
        }
        float cm = fmaxf(x, __shfl_xor_sync(~0u, x, 8));
        cm = fmaxf(cm, __shfl_xor_sync(~0u, cm, 16));
        float mnew = fmaxf(mrun, cm);
        float fsc = __expf(mrun - mnew);   // 0 when mrun==-inf
        float ex = __expf(x - mnew);       // 0 for invalid lanes
        float cs = ex + __shfl_xor_sync(~0u, ex, 8);
        cs += __shfl_xor_sync(~0u, cs, 16);
        srun = srun * fsc + cs;
        mrun = mnew;
        float f2 = __shfl_sync(~0u, fsc, h_a);
        acc.x *= f2; acc.y *= f2; acc.z *= f2; acc.w *= f2;
        #pragma unroll
        for (int q = 0; q < 4; q++) {
            if (q >= n) break;                       // uniform across warp
            float wq = __shfl_sync(~0u, ex, q * 8 + h_a);
            int sq = __shfl_sync(~0u, s, q * 8);
            float4 v = *(const float4*)&g_Vh[(size_t)sq * 128 + lane * 4];
            acc.x += wq * v.x; acc.y += wq * v.y;
            acc.z += wq * v.z; acc.w += wq * v.w;
        }
    }
    float denom = __shfl_sync(~0u, srun, h_a) + 1e-16f;
    float inv = 1.f / denom;
    float4 o = make_float4(acc.x * inv, acc.y * inv, acc.z * inv, acc.w * inv);
    ((float4*)out)[(size_t)gw * 32 + lane] = o;
}

// ---------------- launch ----------------
extern "C" void kernel_launch(void* const* d_in, const int* in_sizes, int n_in,
                              void* d_out, int out_size) {
    const float* attr = (const float*)d_in[0];
    const int*   eeiw = (const int*)d_in[1];   // index buffer viewed as words
    // d_in[2]=Wq, d_in[3]=bq : algebraically cancelled in segment softmax.
    const float* Wk   = (const float*)d_in[4];
    const float* bk   = (const float*)d_in[5];
    const float* Wv   = (const float*)d_in[6];
    const float* bv   = (const float*)d_in[7];
    const float* Aw   = (const float*)d_in[8];
    float*       out  = (float*)d_out;

    prep_kernel   <<<391, 256>>>(Wk, bk, Aw);
    detect_kernel <<<3907, 256>>>(eeiw);
    decode_kernel <<<3907, 256>>>(eeiw);          // + fused histogram
    gemm_v_kernel <<<1563, 256>>>(attr, Wv, bv);  // + fused kA
    scan_a        <<<391, 256>>>();
    scan_b        <<<1, 512>>>();
    scan_c        <<<391, 256>>>();
    scatter_kernel<<<3907, 256>>>();
    agg_kernel    <<<12500, 256>>>(out);

    (void)in_sizes; (void)n_in; (void)out_size;
}

// round 12
// speedup vs baseline: 1.1333x; 1.1170x over previous
#include <cuda_runtime.h>
#include <cuda_bf16.h>
#include <cstdint>

#define E_EDGES 100000
#define M_PAIRS 1000000

// ---------------- device scratch (static, no allocation) ----------------
__device__ float g_WkA[128 * 8];
__device__ float g_bkA[8];
__device__ float g_kA[E_EDGES * 8];
__device__ float g_Vh[(size_t)E_EDGES * 128];
__device__ int   g_counts[E_EDGES];
__device__ int   g_offsets[E_EDGES + 1];
__device__ int   g_cursor[E_EDGES];
__device__ int   g_perm[M_PAIRS];
__device__ int   g_src[M_PAIRS];
__device__ int   g_dst[M_PAIRS];
__device__ int   g_bsum[512];
__device__ int   g_boff[512];
__device__ int   g_is64;

// ---------------- HMMA m16n8k16 bf16 (plain sm_80+ PTX, no 'a' feature) --
__device__ __forceinline__ void mma16816(float* d, const uint32_t* a,
                                         uint32_t b0, uint32_t b1) {
    asm volatile(
        "mma.sync.aligned.m16n8k16.row.col.f32.bf16.bf16.f32 "
        "{%0,%1,%2,%3}, {%4,%5,%6,%7}, {%8,%9}, {%0,%1,%2,%3};\n"
        : "+f"(d[0]), "+f"(d[1]), "+f"(d[2]), "+f"(d[3])
        : "r"(a[0]), "r"(a[1]), "r"(a[2]), "r"(a[3]), "r"(b0), "r"(b1));
}

__device__ __forceinline__ uint32_t pack_bf16(float x, float y) {
    __nv_bfloat16 h0 = __float2bfloat16(x);
    __nv_bfloat16 h1 = __float2bfloat16(y);
    return (uint32_t)__bfloat16_as_ushort(h0) |
           ((uint32_t)__bfloat16_as_ushort(h1) << 16);
}
__device__ __forceinline__ uint32_t pack_lo(float x, float y,
                                            uint32_t hipack) {
    __nv_bfloat16 h0 = __ushort_as_bfloat16((unsigned short)(hipack & 0xFFFF));
    __nv_bfloat16 h1 = __ushort_as_bfloat16((unsigned short)(hipack >> 16));
    return pack_bf16(x - __bfloat162float(h0), y - __bfloat162float(h1));
}

// ---------------- K1: V GEMM via HMMA, split-bf16 ------------------------
// block: 256 thr, 32 rows x 128 cols (100000 = 3125*32, no bounds checks).
// k in 2 chunks of 64. smem 46.1KB (< 48KB default).
// warp: rows rt..rt+15, cols cb..cb+31 (4 n-tiles); 16 accum regs.
__global__ void __launch_bounds__(256)
gemm_v_mma(const float* __restrict__ attr,
           const float* __restrict__ Wv,
           const float* __restrict__ bv) {
    __shared__ __nv_bfloat16 sWhi[128][72];   // W^T [n][k-chunk], 18.4KB
    __shared__ __nv_bfloat16 sWlo[128][72];
    __shared__ __nv_bfloat16 sAhi[32][72];    // A [row][k-chunk], 4.6KB
    __shared__ __nv_bfloat16 sAlo[32][72];

    int tid = threadIdx.x;
    int lane = tid & 31, wid = tid >> 5;
    int g = lane >> 2, tig = lane & 3;
    int row0 = blockIdx.x * 32;
    int rt = (wid & 1) * 16;
    int cb = (wid >> 1) * 32;

    float acc[4][4];
    #pragma unroll
    for (int j = 0; j < 4; j++)
        #pragma unroll
        for (int q = 0; q < 4; q++) acc[j][q] = 0.f;

    for (int c = 0; c < 2; c++) {
        int k0 = c * 64;
        __syncthreads();
        // ---- A chunk fill: 32 rows x 64 k (paired) ----
        #pragma unroll
        for (int idx = tid; idx < 1024; idx += 256) {
            int r = idx >> 5, kp = idx & 31;
            float2 v = *(const float2*)(attr + (size_t)(row0 + r) * 128
                                        + k0 + 2 * kp);
            uint32_t ph = pack_bf16(v.x, v.y);
            uint32_t pl = pack_lo(v.x, v.y, ph);
            *(uint32_t*)&sAhi[r][2 * kp] = ph;
            *(uint32_t*)&sAlo[r][2 * kp] = pl;
        }
        // ---- W chunk fill (transpose): sW[n][k] = Wv[k0+k][n] ----
        #pragma unroll
        for (int idx = tid; idx < 4096; idx += 256) {
            int n = idx & 127, kp = idx >> 7;
            float w0 = Wv[(size_t)(k0 + 2 * kp) * 128 + n];
            float w1 = Wv[(size_t)(k0 + 2 * kp + 1) * 128 + n];
            uint32_t ph = pack_bf16(w0, w1);
            uint32_t pl = pack_lo(w0, w1, ph);
            *(uint32_t*)&sWhi[n][2 * kp] = ph;
            *(uint32_t*)&sWlo[n][2 * kp] = pl;
        }
        __syncthreads();

        #pragma unroll
        for (int ks = 0; ks < 4; ks++) {
            int kk = ks * 16;
            uint32_t ah[4], al[4];
            ah[0] = *(const uint32_t*)&sAhi[rt + g][kk + 2 * tig];
            ah[1] = *(const uint32_t*)&sAhi[rt + g + 8][kk + 2 * tig];
            ah[2] = *(const uint32_t*)&sAhi[rt + g][kk + 2 * tig + 8];
            ah[3] = *(const uint32_t*)&sAhi[rt + g + 8][kk + 2 * tig + 8];
            al[0] = *(const uint32_t*)&sAlo[rt + g][kk + 2 * tig];
            al[1] = *(const uint32_t*)&sAlo[rt + g + 8][kk + 2 * tig];
            al[2] = *(const uint32_t*)&sAlo[rt + g][kk + 2 * tig + 8];
            al[3] = *(const uint32_t*)&sAlo[rt + g + 8][kk + 2 * tig + 8];
            #pragma unroll
            for (int j = 0; j < 4; j++) {
                int n0 = cb + j * 8 + g;
                uint32_t bh0 = *(const uint32_t*)&sWhi[n0][kk + 2 * tig];
                uint32_t bh1 = *(const uint32_t*)&sWhi[n0][kk + 2 * tig + 8];
                uint32_t bl0 = *(const uint32_t*)&sWlo[n0][kk + 2 * tig];
                uint32_t bl1 = *(const uint32_t*)&sWlo[n0][kk + 2 * tig + 8];
                mma16816(acc[j], ah, bh0, bh1);   // Ahi*Whi
                mma16816(acc[j], al, bh0, bh1);   // Alo*Whi
                mma16816(acc[j], ah, bl0, bl1);   // Ahi*Wlo
            }
        }
    }

    // ---- epilogue: d0,d1 -> (row g), d2,d3 -> (row g+8) ----
    #pragma unroll
    for (int j = 0; j < 4; j++) {
        int col = cb + j * 8 + 2 * tig;
        float2 bb = *(const float2*)(bv + col);
        int rglob = row0 + rt + g;
        float2 o0 = make_float2(acc[j][0] + bb.x, acc[j][1] + bb.y);
        float2 o1 = make_float2(acc[j][2] + bb.x, acc[j][3] + bb.y);
        *(float2*)&g_Vh[(size_t)rglob * 128 + col] = o0;
        *(float2*)&g_Vh[(size_t)(rglob + 8) * 128 + col] = o1;
    }
}

// ---------------- K-1a: detect index dtype ----------------
__global__ void detect_kernel(const int* __restrict__ w) {
    int i = blockIdx.x * blockDim.x + threadIdx.x;
    if (i < M_PAIRS) {
        if (w[2 * i + 1] != 0) g_is64 = 0;
    }
}

// ---------------- K-1b: decode indices + fused histogram ----------------
__global__ void decode_kernel(const int* __restrict__ w) {
    int i = blockIdx.x * blockDim.x + threadIdx.x;
    if (i >= M_PAIRS) return;
    int s, d;
    if (g_is64) {
        s = w[2 * i];
        d = w[2 * M_PAIRS + 2 * i];
    } else {
        s = w[i];
        d = w[M_PAIRS + i];
    }
    s = min(max(s, 0), E_EDGES - 1);
    d = min(max(d, 0), E_EDGES - 1);
    g_src[i] = s;
    g_dst[i] = d;
    atomicAdd(&g_counts[d], 1);
}

// ---------------- K0: fold Wk*Aw, zero counts, init flag ----------------
__global__ void prep_kernel(const float* __restrict__ Wk,
                            const float* __restrict__ bk,
                            const float* __restrict__ Aw) {
    int idx = blockIdx.x * blockDim.x + threadIdx.x;
    if (idx < E_EDGES) g_counts[idx] = 0;
    if (idx == 0) g_is64 = 1;
    if (blockIdx.x == 0) {
        int t = threadIdx.x;
        if (t < 128) {
            #pragma unroll
            for (int h = 0; h < 8; h++) {
                float s = 0.f;
                #pragma unroll
                for (int d = 0; d < 16; d++)
                    s += Wk[t * 128 + h * 16 + d] * Aw[d * 8 + h];
                g_WkA[t * 8 + h] = s;
            }
        }
        if (t < 8) {
            float s = 0.f;
            #pragma unroll
            for (int d = 0; d < 16; d++)
                s += bk[t * 16 + d] * Aw[d * 8 + t];
            g_bkA[t] = s;
        }
    }
}

// ---------------- K2: kA = attr @ WkA + bkA (round-4 proven) ------------
__global__ void ka_kernel(const float* __restrict__ attr) {
    __shared__ float sA[32][132];
    __shared__ float sW[1024];
    int t = threadIdx.x;
    for (int i = t; i < 1024; i += 256) sW[i] = g_WkA[i];
    int row0 = blockIdx.x * 32;
    for (int i = t; i < 1024; i += 256) {
        int r = i >> 5, kq = i & 31;
        float4 v = make_float4(0.f, 0.f, 0.f, 0.f);
        if (row0 + r < E_EDGES)
            v = ((const float4*)attr)[(size_t)(row0 + r) * 32 + kq];
        sA[r][kq * 4 + 0] = v.x; sA[r][kq * 4 + 1] = v.y;
        sA[r][kq * 4 + 2] = v.z; sA[r][kq * 4 + 3] = v.w;
    }
    __syncthreads();
    int r = t >> 3, h = t & 7;
    int e = row0 + r;
    if (e < E_EDGES) {
        float acc = g_bkA[h];
        #pragma unroll 16
        for (int k = 0; k < 128; k++)
            acc += sA[r][k] * sW[k * 8 + h];
        g_kA[e * 8 + h] = acc;
    }
}

// ---------------- K4: 3-kernel exclusive scan ----------------
__global__ void scan_a() {
    int i = blockIdx.x * 256 + threadIdx.x;
    int v = (i < E_EDGES) ? g_counts[i] : 0;
    __shared__ int smw[8];
    for (int o = 16; o; o >>= 1) v += __shfl_down_sync(~0u, v, o);
    if ((threadIdx.x & 31) == 0) smw[threadIdx.x >> 5] = v;
    __syncthreads();
    if (threadIdx.x == 0) {
        int s = 0;
        #pragma unroll
        for (int w = 0; w < 8; w++) s += smw[w];
        g_bsum[blockIdx.x] = s;
    }
}

__global__ void scan_b() {
    int t = threadIdx.x;
    int v = (t < 391) ? g_bsum[t] : 0;
    int lane = t & 31, w = t >> 5;
    int inc = v;
    for (int o = 1; o < 32; o <<= 1) {
        int x = __shfl_up_sync(~0u, inc, o);
        if (lane >= o) inc += x;
    }
    __shared__ int ws[16];
    if (lane == 31) ws[w] = inc;
    __syncthreads();
    if (w == 0) {
        int s = (lane < 16) ? ws[lane] : 0;
        int inc2 = s;
        for (int o = 1; o < 16; o <<= 1) {
            int x = __shfl_up_sync(~0u, inc2, o);
            if (lane >= o) inc2 += x;
        }
        if (lane < 16) ws[lane] = inc2 - s;
    }
    __syncthreads();
    if (t < 391) g_boff[t] = ws[w] + inc - v;
    if (t == 0) g_offsets[E_EDGES] = M_PAIRS;
}

__global__ void scan_c() {
    int i = blockIdx.x * 256 + threadIdx.x;
    int v = (i < E_EDGES) ? g_counts[i] : 0;
    int lane = threadIdx.x & 31, w = threadIdx.x >> 5;
    int inc = v;
    for (int o = 1; o < 32; o <<= 1) {
        int x = __shfl_up_sync(~0u, inc, o);
        if (lane >= o) inc += x;
    }
    __shared__ int ws[8];
    if (lane == 31) ws[w] = inc;
    __syncthreads();
    if (w == 0 && lane < 8) {
        int s = ws[lane];
        int inc2 = s;
        for (int o = 1; o < 8; o <<= 1) {
            int x = __shfl_up_sync(0xffu, inc2, o);
            if (lane >= o) inc2 += x;
        }
        ws[lane] = inc2 - s;
    }
    __syncthreads();
    int excl = g_boff[blockIdx.x] + ws[w] + inc - v;
    if (i < E_EDGES) { g_offsets[i] = excl; g_cursor[i] = excl; }
}

// ---------------- K5: scatter src into CSR ----------------
__global__ void scatter_kernel() {
    int i = blockIdx.x * blockDim.x + threadIdx.x;
    if (i < M_PAIRS) {
        int pos = atomicAdd(&g_cursor[g_dst[i]], 1);
        g_perm[pos] = g_src[i];
    }
}

// ---------------- K6: per-dst warp — online softmax + weighted V sum ----
__global__ void agg_kernel(float* __restrict__ out) {
    int gw = (blockIdx.x * blockDim.x + threadIdx.x) >> 5;
    int lane = threadIdx.x & 31;
    if (gw >= E_EDGES) return;
    int beg = g_offsets[gw], end = g_offsets[gw + 1];
    const float NEG_INF = __int_as_float(0xff800000);
    int h_s = lane & 7;
    int h_a = lane >> 2;
    float4 acc = make_float4(0.f, 0.f, 0.f, 0.f);
    float mrun = NEG_INF, srun = 0.f;

    for (int base = beg; base < end; base += 4) {
        int n = end - base; if (n > 4) n = 4;
        int p = lane >> 3;
        int s = 0;
        float x = NEG_INF;
        if (p < n) {
            s = g_perm[base + p];
            x = g_kA[s * 8 + h_s];
        }
        float cm = fmaxf(x, __shfl_xor_sync(~0u, x, 8));
        cm = fmaxf(cm, __shfl_xor_sync(~0u, cm, 16));
        float mnew = fmaxf(mrun, cm);
        float fsc = __expf(mrun - mnew);
        float ex = __expf(x - mnew);
        float cs = ex + __shfl_xor_sync(~0u, ex, 8);
        cs += __shfl_xor_sync(~0u, cs, 16);
        srun = srun * fsc + cs;
        mrun = mnew;
        float f2 = __shfl_sync(~0u, fsc, h_a);
        acc.x *= f2; acc.y *= f2; acc.z *= f2; acc.w *= f2;
        #pragma unroll
        for (int q = 0; q < 4; q++) {
            if (q >= n) break;
            float wq = __shfl_sync(~0u, ex, q * 8 + h_a);
            int sq = __shfl_sync(~0u, s, q * 8);
            float4 v = *(const float4*)&g_Vh[(size_t)sq * 128 + lane * 4];
            acc.x += wq * v.x; acc.y += wq * v.y;
            acc.z += wq * v.z; acc.w += wq * v.w;
        }
    }
    float denom = __shfl_sync(~0u, srun, h_a) + 1e-16f;
    float inv = 1.f / denom;
    float4 o = make_float4(acc.x * inv, acc.y * inv, acc.z * inv, acc.w * inv);
    ((float4*)out)[(size_t)gw * 32 + lane] = o;
}

// ---------------- launch ----------------
extern "C" void kernel_launch(void* const* d_in, const int* in_sizes, int n_in,
                              void* d_out, int out_size) {
    const float* attr = (const float*)d_in[0];
    const int*   eeiw = (const int*)d_in[1];
    // d_in[2]=Wq, d_in[3]=bq : algebraically cancelled in segment softmax.
    const float* Wk   = (const float*)d_in[4];
    const float* bk   = (const float*)d_in[5];
    const float* Wv   = (const float*)d_in[6];
    const float* bv   = (const float*)d_in[7];
    const float* Aw   = (const float*)d_in[8];
    float*       out  = (float*)d_out;

    prep_kernel   <<<391, 256>>>(Wk, bk, Aw);
    detect_kernel <<<3907, 256>>>(eeiw);
    decode_kernel <<<3907, 256>>>(eeiw);          // + fused histogram
    gemm_v_mma    <<<3125, 256>>>(attr, Wv, bv);  // HMMA split-bf16
    ka_kernel     <<<3125, 256>>>(attr);
    scan_a        <<<391, 256>>>();
    scan_b        <<<1, 512>>>();
    scan_c        <<<391, 256>>>();
    scatter_kernel<<<3907, 256>>>();
    agg_kernel    <<<12500, 256>>>(out);

    (void)in_sizes; (void)n_in; (void)out_size;
}

// round 14
// speedup vs baseline: 1.2827x; 1.1318x over previous
#include <cuda_runtime.h>
#include <cuda_bf16.h>
#include <cstdint>

#define E_EDGES 100000
#define M_PAIRS 1000000

// ---------------- device scratch (static, no allocation) ----------------
__device__ float g_WkA[128 * 8];
__device__ float g_bkA[8];
__device__ float g_kA[E_EDGES * 8];
__device__ float g_Vh[(size_t)E_EDGES * 128];
__device__ __align__(16) __nv_bfloat16 g_Whi[128 * 128];  // W^T hi [n][k]
__device__ __align__(16) __nv_bfloat16 g_Wlo[128 * 128];  // W^T lo [n][k]
__device__ int   g_counts[E_EDGES];
__device__ int   g_offsets[E_EDGES + 1];
__device__ int   g_cursor[E_EDGES];
__device__ int   g_perm[M_PAIRS];
__device__ int   g_src[M_PAIRS];
__device__ int   g_dst[M_PAIRS];
__device__ int   g_bsum[512];
__device__ int   g_boff[512];
__device__ int   g_is64;

// ---------------- HMMA m16n8k16 bf16 (plain sm_80+ PTX) -----------------
__device__ __forceinline__ void mma16816(float* d, const uint32_t* a,
                                         uint32_t b0, uint32_t b1) {
    asm volatile(
        "mma.sync.aligned.m16n8k16.row.col.f32.bf16.bf16.f32 "
        "{%0,%1,%2,%3}, {%4,%5,%6,%7}, {%8,%9}, {%0,%1,%2,%3};\n"
        : "+f"(d[0]), "+f"(d[1]), "+f"(d[2]), "+f"(d[3])
        : "r"(a[0]), "r"(a[1]), "r"(a[2]), "r"(a[3]), "r"(b0), "r"(b1));
}

__device__ __forceinline__ uint32_t pack_bf16(float x, float y) {
    __nv_bfloat16 h0 = __float2bfloat16(x);
    __nv_bfloat16 h1 = __float2bfloat16(y);
    return (uint32_t)__bfloat16_as_ushort(h0) |
           ((uint32_t)__bfloat16_as_ushort(h1) << 16);
}
__device__ __forceinline__ uint32_t pack_lo(float x, float y,
                                            uint32_t hipack) {
    __nv_bfloat16 h0 = __ushort_as_bfloat16((unsigned short)(hipack & 0xFFFF));
    __nv_bfloat16 h1 = __ushort_as_bfloat16((unsigned short)(hipack >> 16));
    return pack_bf16(x - __bfloat162float(h0), y - __bfloat162float(h1));
}

// ---------------- K1: V GEMM via HMMA, split-bf16, W precomputed --------
// block: 256 thr = 8 warps, 64 rows x 128 cols; k in 4 chunks of 32.
// warp: rows rt..rt+15, cols cb..cb+63 (8 n-tiles); 32 accum regs.
// smem 30.7KB static.
__global__ void __launch_bounds__(256)
gemm_v_mma(const float* __restrict__ attr,
           const float* __restrict__ bv) {
    __shared__ __nv_bfloat16 sWhi[128][40];   // W^T [n][k-chunk], 10.24KB
    __shared__ __nv_bfloat16 sWlo[128][40];
    __shared__ __nv_bfloat16 sAhi[64][40];    // A [row][k-chunk], 5.12KB
    __shared__ __nv_bfloat16 sAlo[64][40];

    int tid = threadIdx.x;
    int lane = tid & 31, wid = tid >> 5;
    int g = lane >> 2, tig = lane & 3;
    int row0 = blockIdx.x * 64;
    int rt = (wid & 3) * 16;
    int cb = (wid >> 2) * 64;

    float acc[8][4];
    #pragma unroll
    for (int j = 0; j < 8; j++)
        #pragma unroll
        for (int q = 0; q < 4; q++) acc[j][q] = 0.f;

    for (int c = 0; c < 4; c++) {
        int k0 = c * 32;
        __syncthreads();
        // ---- A chunk fill: 64 rows x 32 k (16 bf16 pairs per row) ----
        #pragma unroll
        for (int idx = tid; idx < 1024; idx += 256) {
            int r = idx >> 4, kp = idx & 15;
            float2 v = make_float2(0.f, 0.f);
            if (row0 + r < E_EDGES)
                v = *(const float2*)(attr + (size_t)(row0 + r) * 128
                                     + k0 + 2 * kp);
            uint32_t ph = pack_bf16(v.x, v.y);
            uint32_t pl = pack_lo(v.x, v.y, ph);
            *(uint32_t*)&sAhi[r][2 * kp] = ph;
            *(uint32_t*)&sAlo[r][2 * kp] = pl;
        }
        // ---- W chunk fill: pure uint4 copy from precomputed global ----
        #pragma unroll
        for (int idx = tid; idx < 512; idx += 256) {
            int n = idx >> 2, q = idx & 3;
            *(uint4*)&sWhi[n][8 * q] =
                *(const uint4*)&g_Whi[n * 128 + k0 + 8 * q];
            *(uint4*)&sWlo[n][8 * q] =
                *(const uint4*)&g_Wlo[n * 128 + k0 + 8 * q];
        }
        __syncthreads();

        #pragma unroll
        for (int ks = 0; ks < 2; ks++) {
            int kk = ks * 16;
            uint32_t ah[4], al[4];
            ah[0] = *(const uint32_t*)&sAhi[rt + g][kk + 2 * tig];
            ah[1] = *(const uint32_t*)&sAhi[rt + g + 8][kk + 2 * tig];
            ah[2] = *(const uint32_t*)&sAhi[rt + g][kk + 2 * tig + 8];
            ah[3] = *(const uint32_t*)&sAhi[rt + g + 8][kk + 2 * tig + 8];
            al[0] = *(const uint32_t*)&sAlo[rt + g][kk + 2 * tig];
            al[1] = *(const uint32_t*)&sAlo[rt + g + 8][kk + 2 * tig];
            al[2] = *(const uint32_t*)&sAlo[rt + g][kk + 2 * tig + 8];
            al[3] = *(const uint32_t*)&sAlo[rt + g + 8][kk + 2 * tig + 8];
            #pragma unroll
            for (int j = 0; j < 8; j++) {
                int n0 = cb + j * 8 + g;
                uint32_t bh0 = *(const uint32_t*)&sWhi[n0][kk + 2 * tig];
                uint32_t bh1 = *(const uint32_t*)&sWhi[n0][kk + 2 * tig + 8];
                uint32_t bl0 = *(const uint32_t*)&sWlo[n0][kk + 2 * tig];
                uint32_t bl1 = *(const uint32_t*)&sWlo[n0][kk + 2 * tig + 8];
                mma16816(acc[j], ah, bh0, bh1);   // Ahi*Whi
                mma16816(acc[j], al, bh0, bh1);   // Alo*Whi
                mma16816(acc[j], ah, bl0, bl1);   // Ahi*Wlo
            }
        }
    }

    // ---- epilogue ----
    int r0g = row0 + rt + g;
    #pragma unroll
    for (int j = 0; j < 8; j++) {
        int col = cb + j * 8 + 2 * tig;
        float2 bb = *(const float2*)(bv + col);
        if (r0g < E_EDGES) {
            float2 o0 = make_float2(acc[j][0] + bb.x, acc[j][1] + bb.y);
            *(float2*)&g_Vh[(size_t)r0g * 128 + col] = o0;
        }
        if (r0g + 8 < E_EDGES) {
            float2 o1 = make_float2(acc[j][2] + bb.x, acc[j][3] + bb.y);
            *(float2*)&g_Vh[(size_t)(r0g + 8) * 128 + col] = o1;
        }
    }
}

// ---------------- K-1a: detect index dtype (64K-pair sample) ------------
__global__ void detect_kernel(const int* __restrict__ w) {
    int i = blockIdx.x * blockDim.x + threadIdx.x;
    if (i < 65536) {
        if (w[2 * i + 1] != 0) g_is64 = 0;
    }
}

// ---------------- K-1b: decode indices + fused histogram ----------------
__global__ void decode_kernel(const int* __restrict__ w) {
    int i = blockIdx.x * blockDim.x + threadIdx.x;
    if (i >= M_PAIRS) return;
    int s, d;
    if (g_is64) {
        s = w[2 * i];
        d = w[2 * M_PAIRS + 2 * i];
    } else {
        s = w[i];
        d = w[M_PAIRS + i];
    }
    s = min(max(s, 0), E_EDGES - 1);
    d = min(max(d, 0), E_EDGES - 1);
    g_src[i] = s;
    g_dst[i] = d;
    atomicAdd(&g_counts[d], 1);
}

// ---------------- K0: fold Wk*Aw, split Wv, zero counts -----------------
__global__ void prep_kernel(const float* __restrict__ Wk,
                            const float* __restrict__ bk,
                            const float* __restrict__ Aw,
                            const float* __restrict__ Wv) {
    int idx = blockIdx.x * blockDim.x + threadIdx.x;
    if (idx < E_EDGES) g_counts[idx] = 0;
    if (idx == 0) g_is64 = 1;
    // Wv hi/lo split, transposed to [n][k]
    if (idx < 16384) {
        int n = idx & 127, k = idx >> 7;
        float w = Wv[(size_t)k * 128 + n];
        __nv_bfloat16 hi = __float2bfloat16(w);
        __nv_bfloat16 lo = __float2bfloat16(w - __bfloat162float(hi));
        g_Whi[n * 128 + k] = hi;
        g_Wlo[n * 128 + k] = lo;
    }
    if (blockIdx.x == 0) {
        int t = threadIdx.x;
        if (t < 128) {
            #pragma unroll
            for (int h = 0; h < 8; h++) {
                float s = 0.f;
                #pragma unroll
                for (int d = 0; d < 16; d++)
                    s += Wk[t * 128 + h * 16 + d] * Aw[d * 8 + h];
                g_WkA[t * 8 + h] = s;
            }
        }
        if (t < 8) {
            float s = 0.f;
            #pragma unroll
            for (int d = 0; d < 16; d++)
                s += bk[t * 16 + d] * Aw[d * 8 + t];
            g_bkA[t] = s;
        }
    }
}

// ---------------- K2: kA = attr @ WkA + bkA ----------------
__global__ void ka_kernel(const float* __restrict__ attr) {
    __shared__ float sA[32][132];
    __shared__ float sW[1024];
    int t = threadIdx.x;
    for (int i = t; i < 1024; i += 256) sW[i] = g_WkA[i];
    int row0 = blockIdx.x * 32;
    for (int i = t; i < 1024; i += 256) {
        int r = i >> 5, kq = i & 31;
        float4 v = make_float4(0.f, 0.f, 0.f, 0.f);
        if (row0 + r < E_EDGES)
            v = ((const float4*)attr)[(size_t)(row0 + r) * 32 + kq];
        sA[r][kq * 4 + 0] = v.x; sA[r][kq * 4 + 1] = v.y;
        sA[r][kq * 4 + 2] = v.z; sA[r][kq * 4 + 3] = v.w;
    }
    __syncthreads();
    int r = t >> 3, h = t & 7;
    int e = row0 + r;
    if (e < E_EDGES) {
        float acc = g_bkA[h];
        #pragma unroll 16
        for (int k = 0; k < 128; k++)
            acc += sA[r][k] * sW[k * 8 + h];
        g_kA[e * 8 + h] = acc;
    }
}

// ---------------- K4: 3-kernel exclusive scan ----------------
__global__ void scan_a() {
    int i = blockIdx.x * 256 + threadIdx.x;
    int v = (i < E_EDGES) ? g_counts[i] : 0;
    __shared__ int smw[8];
    for (int o = 16; o; o >>= 1) v += __shfl_down_sync(~0u, v, o);
    if ((threadIdx.x & 31) == 0) smw[threadIdx.x >> 5] = v;
    __syncthreads();
    if (threadIdx.x == 0) {
        int s = 0;
        #pragma unroll
        for (int w = 0; w < 8; w++) s += smw[w];
        g_bsum[blockIdx.x] = s;
    }
}

__global__ void scan_b() {
    int t = threadIdx.x;
    int v = (t < 391) ? g_bsum[t] : 0;
    int lane = t & 31, w = t >> 5;
    int inc = v;
    for (int o = 1; o < 32; o <<= 1) {
        int x = __shfl_up_sync(~0u, inc, o);
        if (lane >= o) inc += x;
    }
    __shared__ int ws[16];
    if (lane == 31) ws[w] = inc;
    __syncthreads();
    if (w == 0) {
        int s = (lane < 16) ? ws[lane] : 0;
        int inc2 = s;
        for (int o = 1; o < 16; o <<= 1) {
            int x = __shfl_up_sync(~0u, inc2, o);
            if (lane >= o) inc2 += x;
        }
        if (lane < 16) ws[lane] = inc2 - s;
    }
    __syncthreads();
    if (t < 391) g_boff[t] = ws[w] + inc - v;
    if (t == 0) g_offsets[E_EDGES] = M_PAIRS;
}

__global__ void scan_c() {
    int i = blockIdx.x * 256 + threadIdx.x;
    int v = (i < E_EDGES) ? g_counts[i] : 0;
    int lane = threadIdx.x & 31, w = threadIdx.x >> 5;
    int inc = v;
    for (int o = 1; o < 32; o <<= 1) {
        int x = __shfl_up_sync(~0u, inc, o);
        if (lane >= o) inc += x;
    }
    __shared__ int ws[8];
    if (lane == 31) ws[w] = inc;
    __syncthreads();
    if (w == 0 && lane < 8) {
        int s = ws[lane];
        int inc2 = s;
        for (int o = 1; o < 8; o <<= 1) {
            int x = __shfl_up_sync(0xffu, inc2, o);
            if (lane >= o) inc2 += x;
        }
        ws[lane] = inc2 - s;
    }
    __syncthreads();
    int excl = g_boff[blockIdx.x] + ws[w] + inc - v;
    if (i < E_EDGES) { g_offsets[i] = excl; g_cursor[i] = excl; }
}

// ---------------- K5: scatter src into CSR ----------------
__global__ void scatter_kernel() {
    int i = blockIdx.x * blockDim.x + threadIdx.x;
    if (i < M_PAIRS) {
        int pos = atomicAdd(&g_cursor[g_dst[i]], 1);
        g_perm[pos] = g_src[i];
    }
}

// ---------------- K6: per-dst warp — online softmax + weighted V sum ----
__global__ void agg_kernel(float* __restrict__ out) {
    int gw = (blockIdx.x * blockDim.x + threadIdx.x) >> 5;
    int lane = threadIdx.x & 31;
    if (gw >= E_EDGES) return;
    int beg = g_offsets[gw], end = g_offsets[gw + 1];
    const float NEG_INF = __int_as_float(0xff800000);
    int h_s = lane & 7;
    int h_a = lane >> 2;
    float4 acc = make_float4(0.f, 0.f, 0.f, 0.f);
    float mrun = NEG_INF, srun = 0.f;

    for (int base = beg; base < end; base += 4) {
        int n = end - base; if (n > 4) n = 4;
        int p = lane >> 3;
        int s = 0;
        float x = NEG_INF;
        if (p < n) {
            s = g_perm[base + p];
            x = g_kA[s * 8 + h_s];
        }
        float cm = fmaxf(x, __shfl_xor_sync(~0u, x, 8));
        cm = fmaxf(cm, __shfl_xor_sync(~0u, cm, 16));
        float mnew = fmaxf(mrun, cm);
        float fsc = __expf(mrun - mnew);
        float ex = __expf(x - mnew);
        float cs = ex + __shfl_xor_sync(~0u, ex, 8);
        cs += __shfl_xor_sync(~0u, cs, 16);
        srun = srun * fsc + cs;
        mrun = mnew;
        float f2 = __shfl_sync(~0u, fsc, h_a);
        acc.x *= f2; acc.y *= f2; acc.z *= f2; acc.w *= f2;
        #pragma unroll
        for (int q = 0; q < 4; q++) {
            if (q >= n) break;
            float wq = __shfl_sync(~0u, ex, q * 8 + h_a);
            int sq = __shfl_sync(~0u, s, q * 8);
            float4 v = *(const float4*)&g_Vh[(size_t)sq * 128 + lane * 4];
            acc.x += wq * v.x; acc.y += wq * v.y;
            acc.z += wq * v.z; acc.w += wq * v.w;
        }
    }
    float denom = __shfl_sync(~0u, srun, h_a) + 1e-16f;
    float inv = 1.f / denom;
    float4 o = make_float4(acc.x * inv, acc.y * inv, acc.z * inv, acc.w * inv);
    ((float4*)out)[(size_t)gw * 32 + lane] = o;
}

// ---------------- launch ----------------
extern "C" void kernel_launch(void* const* d_in, const int* in_sizes, int n_in,
                              void* d_out, int out_size) {
    const float* attr = (const float*)d_in[0];
    const int*   eeiw = (const int*)d_in[1];
    // d_in[2]=Wq, d_in[3]=bq : algebraically cancelled in segment softmax.
    const float* Wk   = (const float*)d_in[4];
    const float* bk   = (const float*)d_in[5];
    const float* Wv   = (const float*)d_in[6];
    const float* bv   = (const float*)d_in[7];
    const float* Aw   = (const float*)d_in[8];
    float*       out  = (float*)d_out;

    prep_kernel   <<<391, 256>>>(Wk, bk, Aw, Wv);
    detect_kernel <<<256, 256>>>(eeiw);
    decode_kernel <<<3907, 256>>>(eeiw);       // + fused histogram
    gemm_v_mma    <<<1563, 256>>>(attr, bv);   // HMMA split-bf16, W precomp
    ka_kernel     <<<3125, 256>>>(attr);
    scan_a        <<<391, 256>>>();
    scan_b        <<<1, 512>>>();
    scan_c        <<<391, 256>>>();
    scatter_kernel<<<3907, 256>>>();
    agg_kernel    <<<12500, 256>>>(out);

    (void)in_sizes; (void)n_in; (void)out_size;
}